// round 7
// baseline (speedup 1.0000x reference)
#include <cuda_runtime.h>
#include <cstdint>

// Problem constants (fixed by the reference implementation)
#define DD      8      // z dimension
#define WIDTHX  128    // hidden width of the flow net
#define HIDDENX 64     // hypernet hidden
#define TT      8      // number of time points
#define NSEG    7      // TT-1 segments
#define PSTRIDE 2304   // floats per param set: W(1024) + U(1024) + (s,B)(256)
#define NTIMES  57     // distinct stage times: 28 substeps * 2 + 1

// Precomputed hypernetwork parameters for all 57 stage times.
// Layout per time i: [0,1024) W[w][d], [1024,2048) Ueff[w][d] (=U*sigmoid(G)/128),
// [2048,2304) interleaved (s[w], B[w]) pairs.
__device__ __align__(16) float g_params[NTIMES * PSTRIDE];
__device__ float g_stot[NTIMES];   // S_tot[i] = sum_w s[w]

// ---------------------------------------------------------------------------
// Setup kernel: one block per stage time. Evaluates the hypernet at time t and
// writes the processed parameter set. Accurate tanhf/expf here (cost trivial).
// ---------------------------------------------------------------------------
__global__ void __launch_bounds__(256) hyper_kernel(
    const float* __restrict__ ts,
    const float* __restrict__ w1, const float* __restrict__ b1,
    const float* __restrict__ w2, const float* __restrict__ b2,
    const float* __restrict__ w3, const float* __restrict__ b3)
{
    __shared__ float h1[HIDDENX];
    __shared__ float h2[HIDDENX];
    __shared__ float p[3 * WIDTHX * DD + WIDTHX];   // 3200 floats
    __shared__ float sred[WIDTHX];

    const int i   = blockIdx.x;
    const int tid = threadIdx.x;

    // Stage time for index i: i in [0,56). i=2j -> substep start, i=2j+1 -> midpoint.
    float t;
    if (i == NTIMES - 1) {
        t = ts[TT - 1];
    } else {
        const int seg  = i >> 3;          // 8 half-steps per segment
        const int r    = i & 7;
        const int k    = r >> 1;          // substep within segment
        const int half = r & 1;
        const float dtseg = (ts[seg + 1] - ts[seg]) * 0.25f;
        t = ts[seg] + (float)k * dtseg + (float)half * (0.5f * dtseg);
    }

    if (tid < HIDDENX) h1[tid] = tanhf(w1[tid] * t + b1[tid]);
    __syncthreads();

    if (tid < HIDDENX) {
        float a = b2[tid];
        const float* row = w2 + tid * HIDDENX;
        #pragma unroll 8
        for (int j = 0; j < HIDDENX; ++j) a = fmaf(row[j], h1[j], a);
        h2[tid] = tanhf(a);
    }
    __syncthreads();

    // p = w3 @ h2 + b3 : warp-per-row (coalesced loads of w3 rows)
    {
        const int warp = tid >> 5, lane = tid & 31;
        const float hA = h2[lane];
        const float hB = h2[lane + 32];
        for (int r = warp; r < 3 * WIDTHX * DD + WIDTHX; r += 8) {
            const float* row = w3 + (size_t)r * HIDDENX;
            float a = fmaf(row[lane], hA, row[lane + 32] * hB);
            #pragma unroll
            for (int off = 16; off > 0; off >>= 1)
                a += __shfl_xor_sync(0xffffffffu, a, off);
            if (lane == 0) p[r] = a + b3[r];
        }
    }
    __syncthreads();

    // Post-process into the packed parameter block for this time.
    float* gp = g_params + (size_t)i * PSTRIDE;
    if (tid < WIDTHX) {
        const int w = tid;
        float s = 0.f;
        #pragma unroll
        for (int d = 0; d < DD; ++d) {
            const float Wv = p[w * DD + d];
            const float Uv = p[WIDTHX * DD + w * DD + d];
            const float Gv = p[2 * WIDTHX * DD + w * DD + d];
            const float sg = 1.f / (1.f + expf(-Gv));
            const float Ue = Uv * sg * (1.f / (float)WIDTHX);
            gp[w * DD + d]               = Wv;
            gp[WIDTHX * DD + w * DD + d] = Ue;
            s = fmaf(Wv, Ue, s);
        }
        gp[2 * WIDTHX * DD + 2 * w]     = s;                       // s[w]
        gp[2 * WIDTHX * DD + 2 * w + 1] = p[3 * WIDTHX * DD + w];  // B[w]
        sred[w] = s;
    }
    __syncthreads();
    if (tid == 0) {
        float S = 0.f;
        for (int w = 0; w < WIDTHX; ++w) S += sred[w];
        g_stot[i] = S;
    }
}

// ---------------------------------------------------------------------------
// RHS evaluation: dz = sum_w tanh(W_w·z + B_w) * Ueff_w ;
// dlogp = -tr = Stot_correction: -tr = sum_w h^2 * s_w - S_tot.
// Params read from shared memory (uniform across warp -> broadcast, no conflicts).
// tanh(a) = 1 - 2/(exp(2a)+1) via ex2.approx + rcp.approx: robust for all a
// (a->+inf: e=inf, rcp=0, h=1; a->-inf: e=0, h=-1), abs err ~3e-7.
// ---------------------------------------------------------------------------
__device__ __forceinline__ void rhs_eval(const float* __restrict__ sp, float Stot,
                                         const float z[DD], float kz[DD], float& kl)
{
    const float4* __restrict__ Wq = (const float4*)sp;
    const float4* __restrict__ Uq = (const float4*)(sp + WIDTHX * DD);
    const float2* __restrict__ SB = (const float2*)(sp + 2 * WIDTHX * DD);

    float d0 = 0.f, d1 = 0.f, d2 = 0.f, d3 = 0.f;
    float d4 = 0.f, d5 = 0.f, d6 = 0.f, d7 = 0.f;
    float hhs = 0.f;

    #pragma unroll 8
    for (int w = 0; w < WIDTHX; ++w) {
        const float4 w0  = Wq[2 * w];
        const float4 w1v = Wq[2 * w + 1];
        const float2 sb  = SB[w];
        float a = sb.y;
        a = fmaf(w0.x,  z[0], a);
        a = fmaf(w0.y,  z[1], a);
        a = fmaf(w0.z,  z[2], a);
        a = fmaf(w0.w,  z[3], a);
        a = fmaf(w1v.x, z[4], a);
        a = fmaf(w1v.y, z[5], a);
        a = fmaf(w1v.z, z[6], a);
        a = fmaf(w1v.w, z[7], a);

        const float arg = a * 2.8853900817779268f;   // 2*log2(e)
        float e;
        asm("ex2.approx.f32 %0, %1;" : "=f"(e) : "f"(arg));
        const float ep1 = e + 1.0f;
        float rr;
        asm("rcp.approx.f32 %0, %1;" : "=f"(rr) : "f"(ep1));
        const float h = fmaf(-2.0f, rr, 1.0f);        // tanh(a)

        const float4 u0 = Uq[2 * w];
        const float4 u1 = Uq[2 * w + 1];
        d0 = fmaf(h, u0.x, d0);
        d1 = fmaf(h, u0.y, d1);
        d2 = fmaf(h, u0.z, d2);
        d3 = fmaf(h, u0.w, d3);
        d4 = fmaf(h, u1.x, d4);
        d5 = fmaf(h, u1.y, d5);
        d6 = fmaf(h, u1.z, d6);
        d7 = fmaf(h, u1.w, d7);
        hhs = fmaf(h * h, sb.x, hhs);
    }
    kz[0] = d0; kz[1] = d1; kz[2] = d2; kz[3] = d3;
    kz[4] = d4; kz[5] = d5; kz[6] = d6; kz[7] = d7;
    kl = hhs - Stot;   // dlogp/dt = -trace
}

// ---------------------------------------------------------------------------
// Main integrator: one thread per sample, z[8]+logp register-resident for the
// whole 28-substep RK4 integration. Per substep the 3 needed param sets
// (times 2j, 2j+1, 2j+2 — contiguous) are staged into shared memory.
// ---------------------------------------------------------------------------
__global__ void __launch_bounds__(128, 4) cnf_kernel(
    const float* __restrict__ ts,
    const float* __restrict__ z0,
    const float* __restrict__ lp0,
    float* __restrict__ out,
    int N)
{
    __shared__ __align__(16) float sp[3 * PSTRIDE];   // 27648 B

    const int n = blockIdx.x * 128 + threadIdx.x;
    const bool active = (n < N);
    const size_t LOFF = (size_t)TT * (size_t)N * DD;  // start of logp block

    float z[DD];
    float lp = 0.f;
    if (active) {
        const float4 za = ((const float4*)z0)[2 * n];
        const float4 zb = ((const float4*)z0)[2 * n + 1];
        z[0] = za.x; z[1] = za.y; z[2] = za.z; z[3] = za.w;
        z[4] = zb.x; z[5] = zb.y; z[6] = zb.z; z[7] = zb.w;
        lp = lp0[n];
        // t=0 outputs
        ((float4*)out)[2 * n]     = za;
        ((float4*)out)[2 * n + 1] = zb;
        out[LOFF + n] = lp;
    } else {
        #pragma unroll
        for (int d = 0; d < DD; ++d) z[d] = 0.f;
    }

    #pragma unroll 1
    for (int seg = 0; seg < NSEG; ++seg) {
        const float dt    = (ts[seg + 1] - ts[seg]) * 0.25f;
        const float hdt   = 0.5f * dt;
        const float sixth = dt * (1.0f / 6.0f);

        #pragma unroll 1
        for (int sub = 0; sub < 4; ++sub) {
            const int j = seg * 4 + sub;

            __syncthreads();
            {   // stage param sets for times 2j, 2j+1, 2j+2 (contiguous in global)
                const float4* src = (const float4*)(g_params + (size_t)(2 * j) * PSTRIDE);
                float4* dst = (float4*)sp;
                for (int q = threadIdx.x; q < (3 * PSTRIDE) / 4; q += 128)
                    dst[q] = src[q];
            }
            __syncthreads();

            const float S0 = g_stot[2 * j];
            const float S1 = g_stot[2 * j + 1];
            const float S2 = g_stot[2 * j + 2];
            const float* pA = sp;
            const float* pM = sp + PSTRIDE;
            const float* pE = sp + 2 * PSTRIDE;

            float kz[DD], zs[DD], az[DD], kl, al;

            // k1
            rhs_eval(pA, S0, z, kz, kl);
            #pragma unroll
            for (int d = 0; d < DD; ++d) { az[d] = kz[d]; zs[d] = fmaf(hdt, kz[d], z[d]); }
            al = kl;
            // k2
            rhs_eval(pM, S1, zs, kz, kl);
            #pragma unroll
            for (int d = 0; d < DD; ++d) { az[d] = fmaf(2.f, kz[d], az[d]); zs[d] = fmaf(hdt, kz[d], z[d]); }
            al = fmaf(2.f, kl, al);
            // k3
            rhs_eval(pM, S1, zs, kz, kl);
            #pragma unroll
            for (int d = 0; d < DD; ++d) { az[d] = fmaf(2.f, kz[d], az[d]); zs[d] = fmaf(dt, kz[d], z[d]); }
            al = fmaf(2.f, kl, al);
            // k4
            rhs_eval(pE, S2, zs, kz, kl);
            #pragma unroll
            for (int d = 0; d < DD; ++d) z[d] = fmaf(sixth, az[d] + kz[d], z[d]);
            lp = fmaf(sixth, al + kl, lp);
        }

        if (active) {
            const size_t zo = ((size_t)(seg + 1) * N + n) * DD;
            *(float4*)(out + zo)     = make_float4(z[0], z[1], z[2], z[3]);
            *(float4*)(out + zo + 4) = make_float4(z[4], z[5], z[6], z[7]);
            out[LOFF + (size_t)(seg + 1) * N + n] = lp;
        }
    }
}

// ---------------------------------------------------------------------------
// Launch. Inputs (metadata order): ts, z0, logp_diff_t0, w1, b1, w2, b2, w3, b3.
// Output: concat(zt[T,N,D], logp_t[T,N,1]) as float32.
// ---------------------------------------------------------------------------
extern "C" void kernel_launch(void* const* d_in, const int* in_sizes, int n_in,
                              void* d_out, int out_size)
{
    const float* ts  = (const float*)d_in[0];
    const float* z0  = (const float*)d_in[1];
    const float* lp0 = (const float*)d_in[2];
    const float* w1  = (const float*)d_in[3];
    const float* b1  = (const float*)d_in[4];
    const float* w2  = (const float*)d_in[5];
    const float* b2  = (const float*)d_in[6];
    const float* w3  = (const float*)d_in[7];
    const float* b3  = (const float*)d_in[8];

    const int N = in_sizes[1] / DD;

    hyper_kernel<<<NTIMES, 256>>>(ts, w1, b1, w2, b2, w3, b3);

    const int blocks = (N + 127) / 128;
    cnf_kernel<<<blocks, 128>>>(ts, z0, lp0, (float*)d_out, N);

    (void)n_in; (void)out_size;
}

// round 9
// speedup vs baseline: 1.3078x; 1.3078x over previous
#include <cuda_runtime.h>
#include <cstdint>

// Problem constants (fixed by the reference implementation)
#define DD      8      // z dimension
#define WIDTHX  128    // hidden width of the flow net
#define HIDDENX 64     // hypernet hidden
#define TT      8      // number of time points
#define NSEG    7      // TT-1 segments
#define PSTRIDE 2304   // floats per param set: W(1024) + U(1024) + (s,B)(256)
#define NTIMES  57     // distinct stage times: 28 substeps * 2 + 1

typedef unsigned long long u64p;   // packed f32x2 carrier

// ---- packed f32x2 / MUFU primitives (ptxas never emits FFMA2 from C++) ----
#define FMA2(d, a, b, c) asm("fma.rn.f32x2 %0, %1, %2, %3;" : "=l"(d) : "l"(a), "l"(b), "l"(c))
#define ADD2(d, a, b)    asm("add.rn.f32x2 %0, %1, %2;"     : "=l"(d) : "l"(a), "l"(b))
#define PACK2(d, lo, hi) asm("mov.b64 %0, {%1, %2};"        : "=l"(d) : "f"(lo), "f"(hi))
#define UNPACK2(lo, hi, s) asm("mov.b64 {%0, %1}, %2;"      : "=f"(lo), "=f"(hi) : "l"(s))
#define TANHX(d, a)      asm("tanh.approx.f32 %0, %1;"      : "=f"(d) : "f"(a))

// Precomputed hypernetwork parameters for all 57 stage times.
// Layout per time i: [0,1024) W[w][d], [1024,2048) Ueff[w][d] (=U*sigmoid(G)/128),
// [2048,2304) interleaved (s[w], B[w]) pairs.
__device__ __align__(16) float g_params[NTIMES * PSTRIDE];
__device__ float g_stot[NTIMES];   // S_tot[i] = sum_w s[w]

// ---------------------------------------------------------------------------
// Setup kernel: one block per stage time. Evaluates the hypernet at time t and
// writes the processed parameter set. Accurate tanhf/expf here (cost trivial).
// ---------------------------------------------------------------------------
__global__ void __launch_bounds__(256) hyper_kernel(
    const float* __restrict__ ts,
    const float* __restrict__ w1, const float* __restrict__ b1,
    const float* __restrict__ w2, const float* __restrict__ b2,
    const float* __restrict__ w3, const float* __restrict__ b3)
{
    __shared__ float h1[HIDDENX];
    __shared__ float h2[HIDDENX];
    __shared__ float p[3 * WIDTHX * DD + WIDTHX];   // 3200 floats
    __shared__ float sred[WIDTHX];

    const int i   = blockIdx.x;
    const int tid = threadIdx.x;

    // Stage time for index i: i in [0,56). i=2j -> substep start, i=2j+1 -> midpoint.
    float t;
    if (i == NTIMES - 1) {
        t = ts[TT - 1];
    } else {
        const int seg  = i >> 3;          // 8 half-steps per segment
        const int r    = i & 7;
        const int k    = r >> 1;          // substep within segment
        const int half = r & 1;
        const float dtseg = (ts[seg + 1] - ts[seg]) * 0.25f;
        t = ts[seg] + (float)k * dtseg + (float)half * (0.5f * dtseg);
    }

    if (tid < HIDDENX) h1[tid] = tanhf(w1[tid] * t + b1[tid]);
    __syncthreads();

    if (tid < HIDDENX) {
        float a = b2[tid];
        const float* row = w2 + tid * HIDDENX;
        #pragma unroll 8
        for (int j = 0; j < HIDDENX; ++j) a = fmaf(row[j], h1[j], a);
        h2[tid] = tanhf(a);
    }
    __syncthreads();

    // p = w3 @ h2 + b3 : warp-per-row (coalesced loads of w3 rows)
    {
        const int warp = tid >> 5, lane = tid & 31;
        const float hA = h2[lane];
        const float hB = h2[lane + 32];
        for (int r = warp; r < 3 * WIDTHX * DD + WIDTHX; r += 8) {
            const float* row = w3 + (size_t)r * HIDDENX;
            float a = fmaf(row[lane], hA, row[lane + 32] * hB);
            #pragma unroll
            for (int off = 16; off > 0; off >>= 1)
                a += __shfl_xor_sync(0xffffffffu, a, off);
            if (lane == 0) p[r] = a + b3[r];
        }
    }
    __syncthreads();

    // Post-process into the packed parameter block for this time.
    float* gp = g_params + (size_t)i * PSTRIDE;
    if (tid < WIDTHX) {
        const int w = tid;
        float s = 0.f;
        #pragma unroll
        for (int d = 0; d < DD; ++d) {
            const float Wv = p[w * DD + d];
            const float Uv = p[WIDTHX * DD + w * DD + d];
            const float Gv = p[2 * WIDTHX * DD + w * DD + d];
            const float sg = 1.f / (1.f + expf(-Gv));
            const float Ue = Uv * sg * (1.f / (float)WIDTHX);
            gp[w * DD + d]               = Wv;
            gp[WIDTHX * DD + w * DD + d] = Ue;
            s = fmaf(Wv, Ue, s);
        }
        gp[2 * WIDTHX * DD + 2 * w]     = s;                       // s[w]
        gp[2 * WIDTHX * DD + 2 * w + 1] = p[3 * WIDTHX * DD + w];  // B[w]
        sred[w] = s;
    }
    __syncthreads();
    if (tid == 0) {
        float S = 0.f;
        for (int w = 0; w < WIDTHX; ++w) S += sred[w];
        g_stot[i] = S;
    }
}

// ---------------------------------------------------------------------------
// RHS for TWO samples sharing one pass over the (uniform) parameters.
// State is packed f32x2 pairs: z = {(z0,z1),(z2,z3),(z4,z5),(z6,z7)}.
// dz = sum_w tanh(W_w·z + B_w) * Ueff_w ; dlogp = sum_w h^2 s_w - S_tot.
// ---------------------------------------------------------------------------
__device__ __forceinline__ void rhs_eval2(
    const float* __restrict__ sp, float Stot,
    const u64p zA[4], const u64p zB[4],
    u64p kA[4], u64p kB[4], float& klA, float& klB)
{
    const ulonglong2* __restrict__ Wq = (const ulonglong2*)sp;
    const ulonglong2* __restrict__ Uq = (const ulonglong2*)(sp + WIDTHX * DD);
    const float2*     __restrict__ SB = (const float2*)(sp + 2 * WIDTHX * DD);

    u64p dA0 = 0, dA1 = 0, dA2 = 0, dA3 = 0;   // 0ULL == (0.f, 0.f)
    u64p dB0 = 0, dB1 = 0, dB2 = 0, dB3 = 0;
    float hhsA = 0.f, hhsB = 0.f;
    const float zero = 0.f;

    #pragma unroll 4
    for (int w = 0; w < WIDTHX; ++w) {
        const ulonglong2 wa = Wq[2 * w];       // (w0,w1),(w2,w3)
        const ulonglong2 wb = Wq[2 * w + 1];   // (w4,w5),(w6,w7)
        const float2 sb = SB[w];               // (s, B)
        u64p bias; PACK2(bias, sb.y, zero);

        u64p aA, aB;
        FMA2(aA, wa.x, zA[0], bias);
        FMA2(aB, wa.x, zB[0], bias);
        FMA2(aA, wa.y, zA[1], aA);
        FMA2(aB, wa.y, zB[1], aB);
        FMA2(aA, wb.x, zA[2], aA);
        FMA2(aB, wb.x, zB[2], aB);
        FMA2(aA, wb.y, zA[3], aA);
        FMA2(aB, wb.y, zB[3], aB);

        float aAl, aAh, aBl, aBh;
        UNPACK2(aAl, aAh, aA);
        UNPACK2(aBl, aBh, aB);
        float hA, hB;
        TANHX(hA, aAl + aAh);                  // MUFU.TANH
        TANHX(hB, aBl + aBh);

        const ulonglong2 ua = Uq[2 * w];
        const ulonglong2 ub = Uq[2 * w + 1];
        u64p hA2, hB2;
        PACK2(hA2, hA, hA);
        PACK2(hB2, hB, hB);
        FMA2(dA0, hA2, ua.x, dA0);  FMA2(dB0, hB2, ua.x, dB0);
        FMA2(dA1, hA2, ua.y, dA1);  FMA2(dB1, hB2, ua.y, dB1);
        FMA2(dA2, hA2, ub.x, dA2);  FMA2(dB2, hB2, ub.x, dB2);
        FMA2(dA3, hA2, ub.y, dA3);  FMA2(dB3, hB2, ub.y, dB3);

        hhsA = fmaf(hA * hA, sb.x, hhsA);
        hhsB = fmaf(hB * hB, sb.x, hhsB);
    }
    kA[0] = dA0; kA[1] = dA1; kA[2] = dA2; kA[3] = dA3;
    kB[0] = dB0; kB[1] = dB1; kB[2] = dB2; kB[3] = dB3;
    klA = hhsA - Stot;
    klB = hhsB - Stot;
}

// ---------------------------------------------------------------------------
// Main integrator: 64 threads/block, 2 samples/thread (n0 and n0+64), z/logp
// register-resident (packed f32x2) for the whole 28-substep RK4 integration.
// Param sets staged in a 3-slot rotating smem buffer (slot = time_index % 3):
// substep j needs times 2j, 2j+1, 2j+2; time 2j persists from previous substep,
// so only 2 sets are loaded per substep after the first.
// ---------------------------------------------------------------------------
__global__ void __launch_bounds__(64) cnf_kernel(
    const float* __restrict__ ts,
    const float* __restrict__ z0,
    const float* __restrict__ lp0,
    float* __restrict__ out,
    int N)
{
    __shared__ __align__(16) float sp[3 * PSTRIDE];   // 27648 B

    const int tid = threadIdx.x;
    const int n0 = blockIdx.x * 128 + tid;
    const int n1 = n0 + 64;
    const bool act0 = (n0 < N);
    const bool act1 = (n1 < N);
    const size_t LOFF = (size_t)TT * (size_t)N * DD;  // start of logp block

    u64p zA[4], zB[4];
    float lpA = 0.f, lpB = 0.f;
    if (act0) {
        const ulonglong2 a0 = ((const ulonglong2*)z0)[2 * n0];
        const ulonglong2 a1 = ((const ulonglong2*)z0)[2 * n0 + 1];
        zA[0] = a0.x; zA[1] = a0.y; zA[2] = a1.x; zA[3] = a1.y;
        lpA = lp0[n0];
        ((ulonglong2*)out)[2 * n0]     = a0;   // t=0 outputs
        ((ulonglong2*)out)[2 * n0 + 1] = a1;
        out[LOFF + n0] = lpA;
    } else { zA[0] = zA[1] = zA[2] = zA[3] = 0; }
    if (act1) {
        const ulonglong2 b0 = ((const ulonglong2*)z0)[2 * n1];
        const ulonglong2 b1 = ((const ulonglong2*)z0)[2 * n1 + 1];
        zB[0] = b0.x; zB[1] = b0.y; zB[2] = b1.x; zB[3] = b1.y;
        lpB = lp0[n1];
        ((ulonglong2*)out)[2 * n1]     = b0;
        ((ulonglong2*)out)[2 * n1 + 1] = b1;
        out[LOFF + n1] = lpB;
    } else { zB[0] = zB[1] = zB[2] = zB[3] = 0; }

    #pragma unroll 1
    for (int seg = 0; seg < NSEG; ++seg) {
        const float dt    = (ts[seg + 1] - ts[seg]) * 0.25f;
        const float hdt   = 0.5f * dt;
        const float sixth = dt * (1.0f / 6.0f);
        const float two   = 2.0f;
        u64p hdt2, dt2, sixth2, two2;
        PACK2(hdt2, hdt, hdt);
        PACK2(dt2, dt, dt);
        PACK2(sixth2, sixth, sixth);
        PACK2(two2, two, two);

        #pragma unroll 1
        for (int sub = 0; sub < 4; ++sub) {
            const int j = seg * 4 + sub;

            __syncthreads();   // previous substep done before slots overwritten
            if (j == 0) {      // load times 0,1,2 into slots 0,1,2 (contiguous)
                const float4* src = (const float4*)g_params;
                float4* dst = (float4*)sp;
                for (int q = tid; q < 3 * (PSTRIDE / 4); q += 64) dst[q] = src[q];
            } else {           // time 2j already resident; load 2j+1 and 2j+2
                const int tm = 2 * j + 1, te = 2 * j + 2;
                const float4* s1 = (const float4*)(g_params + (size_t)tm * PSTRIDE);
                const float4* s2 = (const float4*)(g_params + (size_t)te * PSTRIDE);
                float4* d1 = (float4*)(sp + (size_t)(tm % 3) * PSTRIDE);
                float4* d2 = (float4*)(sp + (size_t)(te % 3) * PSTRIDE);
                for (int q = tid; q < PSTRIDE / 4; q += 64) { d1[q] = s1[q]; d2[q] = s2[q]; }
            }
            __syncthreads();

            const float S0 = g_stot[2 * j];
            const float S1 = g_stot[2 * j + 1];
            const float S2 = g_stot[2 * j + 2];
            const float* pA = sp + (size_t)((2 * j)     % 3) * PSTRIDE;
            const float* pM = sp + (size_t)((2 * j + 1) % 3) * PSTRIDE;
            const float* pE = sp + (size_t)((2 * j + 2) % 3) * PSTRIDE;

            u64p kzA[4], kzB[4], azA[4], azB[4], zsA[4], zsB[4];
            float klA, klB, alA, alB;

            // k1
            rhs_eval2(pA, S0, zA, zB, kzA, kzB, klA, klB);
            #pragma unroll
            for (int d = 0; d < 4; ++d) {
                azA[d] = kzA[d];                    azB[d] = kzB[d];
                FMA2(zsA[d], hdt2, kzA[d], zA[d]);  FMA2(zsB[d], hdt2, kzB[d], zB[d]);
            }
            alA = klA; alB = klB;
            // k2
            rhs_eval2(pM, S1, zsA, zsB, kzA, kzB, klA, klB);
            #pragma unroll
            for (int d = 0; d < 4; ++d) {
                FMA2(azA[d], two2, kzA[d], azA[d]); FMA2(azB[d], two2, kzB[d], azB[d]);
                FMA2(zsA[d], hdt2, kzA[d], zA[d]);  FMA2(zsB[d], hdt2, kzB[d], zB[d]);
            }
            alA = fmaf(two, klA, alA); alB = fmaf(two, klB, alB);
            // k3
            rhs_eval2(pM, S1, zsA, zsB, kzA, kzB, klA, klB);
            #pragma unroll
            for (int d = 0; d < 4; ++d) {
                FMA2(azA[d], two2, kzA[d], azA[d]); FMA2(azB[d], two2, kzB[d], azB[d]);
                FMA2(zsA[d], dt2, kzA[d], zA[d]);   FMA2(zsB[d], dt2, kzB[d], zB[d]);
            }
            alA = fmaf(two, klA, alA); alB = fmaf(two, klB, alB);
            // k4
            rhs_eval2(pE, S2, zsA, zsB, kzA, kzB, klA, klB);
            #pragma unroll
            for (int d = 0; d < 4; ++d) {
                u64p tA, tB;
                ADD2(tA, azA[d], kzA[d]);           ADD2(tB, azB[d], kzB[d]);
                FMA2(zA[d], sixth2, tA, zA[d]);     FMA2(zB[d], sixth2, tB, zB[d]);
            }
            lpA = fmaf(sixth, alA + klA, lpA);
            lpB = fmaf(sixth, alB + klB, lpB);
        }

        if (act0) {
            const size_t zo = ((size_t)(seg + 1) * N + n0) * DD;
            ((ulonglong2*)(out + zo))[0] = make_ulonglong2(zA[0], zA[1]);
            ((ulonglong2*)(out + zo))[1] = make_ulonglong2(zA[2], zA[3]);
            out[LOFF + (size_t)(seg + 1) * N + n0] = lpA;
        }
        if (act1) {
            const size_t zo = ((size_t)(seg + 1) * N + n1) * DD;
            ((ulonglong2*)(out + zo))[0] = make_ulonglong2(zB[0], zB[1]);
            ((ulonglong2*)(out + zo))[1] = make_ulonglong2(zB[2], zB[3]);
            out[LOFF + (size_t)(seg + 1) * N + n1] = lpB;
        }
    }
}

// ---------------------------------------------------------------------------
// Launch. Inputs (metadata order): ts, z0, logp_diff_t0, w1, b1, w2, b2, w3, b3.
// Output: concat(zt[T,N,D], logp_t[T,N,1]) as float32.
// ---------------------------------------------------------------------------
extern "C" void kernel_launch(void* const* d_in, const int* in_sizes, int n_in,
                              void* d_out, int out_size)
{
    const float* ts  = (const float*)d_in[0];
    const float* z0  = (const float*)d_in[1];
    const float* lp0 = (const float*)d_in[2];
    const float* w1  = (const float*)d_in[3];
    const float* b1  = (const float*)d_in[4];
    const float* w2  = (const float*)d_in[5];
    const float* b2  = (const float*)d_in[6];
    const float* w3  = (const float*)d_in[7];
    const float* b3  = (const float*)d_in[8];

    const int N = in_sizes[1] / DD;

    hyper_kernel<<<NTIMES, 256>>>(ts, w1, b1, w2, b2, w3, b3);

    const int blocks = (N + 127) / 128;   // 2 samples per thread, 64 threads/block
    cnf_kernel<<<blocks, 64>>>(ts, z0, lp0, (float*)d_out, N);

    (void)n_in; (void)out_size;
}

// round 11
// speedup vs baseline: 1.3597x; 1.0397x over previous
#include <cuda_runtime.h>
#include <cstdint>

// Problem constants (fixed by the reference implementation)
#define DD      8      // z dimension
#define WIDTHX  128    // hidden width of the flow net
#define HIDDENX 64     // hypernet hidden
#define TT      8      // number of time points
#define NSEG    7      // TT-1 segments
#define NTIMES  57     // distinct stage times: 28 substeps * 2 + 1

// Packed parameter layout per stage time (floats):
//   [0, 2048)    Wsplat: unit w -> 16 floats (w0,w0,w1,w1,...,w7,w7)
//   [2048, 3072) Ueff dim-paired: unit w -> 8 floats (u0..u7), Ueff=U*sigmoid(G)/128
//   [3072, 3584) SBS: unit w -> 4 floats {B, B, s, s},  s = sum_d W*Ueff
#define PSTRIDE 3584
#define UOFF    2048
#define SOFF    3072

typedef unsigned long long u64p;   // packed f32x2 carrier

// ---- packed f32x2 / MUFU primitives (ptxas never emits FFMA2 from C++) ----
#define FMA2(d, a, b, c) asm("fma.rn.f32x2 %0, %1, %2, %3;" : "=l"(d) : "l"(a), "l"(b), "l"(c))
#define MUL2(d, a, b)    asm("mul.rn.f32x2 %0, %1, %2;"     : "=l"(d) : "l"(a), "l"(b))
#define ADD2(d, a, b)    asm("add.rn.f32x2 %0, %1, %2;"     : "=l"(d) : "l"(a), "l"(b))
#define PACK2(d, lo, hi) asm("mov.b64 %0, {%1, %2};"        : "=l"(d) : "f"(lo), "f"(hi))
#define UNPACK2(lo, hi, s) asm("mov.b64 {%0, %1}, %2;"      : "=f"(lo), "=f"(hi) : "l"(s))
#define TANHX(d, a)      asm("tanh.approx.f32 %0, %1;"      : "=f"(d) : "f"(a))

__device__ __align__(16) float g_params[NTIMES * PSTRIDE];
__device__ float g_stot[NTIMES];   // S_tot[i] = sum_w s[w]

// ---------------------------------------------------------------------------
// Setup kernel: one block per stage time. Evaluates the hypernet at time t and
// writes the processed parameter set in the splatted/packed layout.
// ---------------------------------------------------------------------------
__global__ void __launch_bounds__(256) hyper_kernel(
    const float* __restrict__ ts,
    const float* __restrict__ w1, const float* __restrict__ b1,
    const float* __restrict__ w2, const float* __restrict__ b2,
    const float* __restrict__ w3, const float* __restrict__ b3)
{
    __shared__ float h1[HIDDENX];
    __shared__ float h2[HIDDENX];
    __shared__ float p[3 * WIDTHX * DD + WIDTHX];   // 3200 floats
    __shared__ float sred[WIDTHX];

    const int i   = blockIdx.x;
    const int tid = threadIdx.x;

    // Stage time for index i: i=2j -> substep start, i=2j+1 -> midpoint.
    float t;
    if (i == NTIMES - 1) {
        t = ts[TT - 1];
    } else {
        const int seg  = i >> 3;          // 8 half-steps per segment
        const int r    = i & 7;
        const int k    = r >> 1;          // substep within segment
        const int half = r & 1;
        const float dtseg = (ts[seg + 1] - ts[seg]) * 0.25f;
        t = ts[seg] + (float)k * dtseg + (float)half * (0.5f * dtseg);
    }

    if (tid < HIDDENX) h1[tid] = tanhf(w1[tid] * t + b1[tid]);
    __syncthreads();

    if (tid < HIDDENX) {
        float a = b2[tid];
        const float* row = w2 + tid * HIDDENX;
        #pragma unroll 8
        for (int j = 0; j < HIDDENX; ++j) a = fmaf(row[j], h1[j], a);
        h2[tid] = tanhf(a);
    }
    __syncthreads();

    // p = w3 @ h2 + b3 : warp-per-row (coalesced loads of w3 rows)
    {
        const int warp = tid >> 5, lane = tid & 31;
        const float hA = h2[lane];
        const float hB = h2[lane + 32];
        for (int r = warp; r < 3 * WIDTHX * DD + WIDTHX; r += 8) {
            const float* row = w3 + (size_t)r * HIDDENX;
            float a = fmaf(row[lane], hA, row[lane + 32] * hB);
            #pragma unroll
            for (int off = 16; off > 0; off >>= 1)
                a += __shfl_xor_sync(0xffffffffu, a, off);
            if (lane == 0) p[r] = a + b3[r];
        }
    }
    __syncthreads();

    // Post-process into the packed parameter block for this time.
    float* gp = g_params + (size_t)i * PSTRIDE;
    if (tid < WIDTHX) {
        const int w = tid;
        float s = 0.f;
        #pragma unroll
        for (int d = 0; d < DD; ++d) {
            const float Wv = p[w * DD + d];
            const float Uv = p[WIDTHX * DD + w * DD + d];
            const float Gv = p[2 * WIDTHX * DD + w * DD + d];
            const float sg = 1.f / (1.f + expf(-Gv));
            const float Ue = Uv * sg * (1.f / (float)WIDTHX);
            gp[w * 16 + 2 * d]     = Wv;   // splatted W
            gp[w * 16 + 2 * d + 1] = Wv;
            gp[UOFF + w * DD + d]  = Ue;   // dim-paired Ueff
            s = fmaf(Wv, Ue, s);
        }
        const float Bv = p[3 * WIDTHX * DD + w];
        gp[SOFF + w * 4 + 0] = Bv;
        gp[SOFF + w * 4 + 1] = Bv;
        gp[SOFF + w * 4 + 2] = s;
        gp[SOFF + w * 4 + 3] = s;
        sred[w] = s;
    }
    __syncthreads();
    if (tid == 0) {
        float S = 0.f;
        for (int w = 0; w < WIDTHX; ++w) S += sred[w];
        g_stot[i] = S;
    }
}

// ---------------------------------------------------------------------------
// RHS for TWO samples, state sample-packed: zp[d] = (zA_d, zB_d).
// Per unit: 8 FMA2 dot (no horizontal add!), 2 MUFU.TANH, 8 FMA2 U-accum,
// MUL2+FMA2 packed trace. fma-pipe = 18 ops / unit / 2 samples.
// ---------------------------------------------------------------------------
__device__ __forceinline__ void rhs_eval2(
    const float* __restrict__ sp, float Stot,
    const u64p zp[8], u64p kp[8], float& klA, float& klB)
{
    const ulonglong2* __restrict__ Wq = (const ulonglong2*)sp;          // 4 per unit
    const ulonglong2* __restrict__ Uq = (const ulonglong2*)(sp + UOFF); // 2 per unit
    const ulonglong2* __restrict__ Sq = (const ulonglong2*)(sp + SOFF); // 1 per unit

    u64p dA01 = 0, dA23 = 0, dA45 = 0, dA67 = 0;  // dim-paired dz, sample A
    u64p dB01 = 0, dB23 = 0, dB45 = 0, dB67 = 0;  // dim-paired dz, sample B
    u64p hh2 = 0;                                  // packed (trA, trB) accum

    #pragma unroll 8
    for (int w = 0; w < WIDTHX; ++w) {
        const ulonglong2 wq0 = Wq[4 * w + 0];
        const ulonglong2 wq1 = Wq[4 * w + 1];
        const ulonglong2 wq2 = Wq[4 * w + 2];
        const ulonglong2 wq3 = Wq[4 * w + 3];
        const ulonglong2 sb  = Sq[w];       // .x=(B,B)  .y=(s,s)

        u64p a;
        FMA2(a, wq0.x, zp[0], sb.x);
        FMA2(a, wq0.y, zp[1], a);
        FMA2(a, wq1.x, zp[2], a);
        FMA2(a, wq1.y, zp[3], a);
        FMA2(a, wq2.x, zp[4], a);
        FMA2(a, wq2.y, zp[5], a);
        FMA2(a, wq3.x, zp[6], a);
        FMA2(a, wq3.y, zp[7], a);           // a = (aA, aB)

        float aA, aB; UNPACK2(aA, aB, a);   // register-pair aliasing, ~free
        float hA, hB;
        TANHX(hA, aA);
        TANHX(hB, aB);

        u64p hA2, hB2, hAB;
        PACK2(hA2, hA, hA);
        PACK2(hB2, hB, hB);
        PACK2(hAB, hA, hB);

        const ulonglong2 u0 = Uq[2 * w];
        const ulonglong2 u1 = Uq[2 * w + 1];
        FMA2(dA01, hA2, u0.x, dA01);  FMA2(dB01, hB2, u0.x, dB01);
        FMA2(dA23, hA2, u0.y, dA23);  FMA2(dB23, hB2, u0.y, dB23);
        FMA2(dA45, hA2, u1.x, dA45);  FMA2(dB45, hB2, u1.x, dB45);
        FMA2(dA67, hA2, u1.y, dA67);  FMA2(dB67, hB2, u1.y, dB67);

        u64p hsq;
        MUL2(hsq, hAB, hAB);                // (hA^2, hB^2)
        FMA2(hh2, hsq, sb.y, hh2);          // += h^2 * s, both samples
    }

    // transpose dim-paired -> sample-packed kp[d] = (kA_d, kB_d)
    float a0, a1, b0, b1;
    UNPACK2(a0, a1, dA01); UNPACK2(b0, b1, dB01);
    PACK2(kp[0], a0, b0);  PACK2(kp[1], a1, b1);
    UNPACK2(a0, a1, dA23); UNPACK2(b0, b1, dB23);
    PACK2(kp[2], a0, b0);  PACK2(kp[3], a1, b1);
    UNPACK2(a0, a1, dA45); UNPACK2(b0, b1, dB45);
    PACK2(kp[4], a0, b0);  PACK2(kp[5], a1, b1);
    UNPACK2(a0, a1, dA67); UNPACK2(b0, b1, dB67);
    PACK2(kp[6], a0, b0);  PACK2(kp[7], a1, b1);

    float tA, tB; UNPACK2(tA, tB, hh2);
    klA = tA - Stot;
    klB = tB - Stot;
}

// ---------------------------------------------------------------------------
// Main integrator: 64 threads/block, 2 samples/thread (n0 and n0+64), state
// sample-packed in registers for the whole 28-substep RK4 integration.
// 3-slot rotating smem buffer: substep j needs times 2j,2j+1,2j+2; set 2j
// persists from the previous substep, so only 2 sets are staged per substep.
// ---------------------------------------------------------------------------
__global__ void __launch_bounds__(64, 1) cnf_kernel(
    const float* __restrict__ ts,
    const float* __restrict__ z0,
    const float* __restrict__ lp0,
    float* __restrict__ out,
    int N)
{
    __shared__ __align__(16) float sp[3 * PSTRIDE];   // 43008 B

    const int tid = threadIdx.x;
    const int n0 = blockIdx.x * 128 + tid;
    const int n1 = n0 + 64;
    const bool act0 = (n0 < N);
    const bool act1 = (n1 < N);
    const size_t LOFF = (size_t)TT * (size_t)N * DD;  // start of logp block

    u64p zp[8];
    float lpA = 0.f, lpB = 0.f;
    {
        float zA[8] = {0,0,0,0,0,0,0,0};
        float zB[8] = {0,0,0,0,0,0,0,0};
        if (act0) {
            const float4 a0 = ((const float4*)z0)[2 * n0];
            const float4 a1 = ((const float4*)z0)[2 * n0 + 1];
            zA[0]=a0.x; zA[1]=a0.y; zA[2]=a0.z; zA[3]=a0.w;
            zA[4]=a1.x; zA[5]=a1.y; zA[6]=a1.z; zA[7]=a1.w;
            lpA = lp0[n0];
            ((float4*)out)[2 * n0]     = a0;   // t=0 outputs
            ((float4*)out)[2 * n0 + 1] = a1;
            out[LOFF + n0] = lpA;
        }
        if (act1) {
            const float4 b0 = ((const float4*)z0)[2 * n1];
            const float4 b1 = ((const float4*)z0)[2 * n1 + 1];
            zB[0]=b0.x; zB[1]=b0.y; zB[2]=b0.z; zB[3]=b0.w;
            zB[4]=b1.x; zB[5]=b1.y; zB[6]=b1.z; zB[7]=b1.w;
            lpB = lp0[n1];
            ((float4*)out)[2 * n1]     = b0;
            ((float4*)out)[2 * n1 + 1] = b1;
            out[LOFF + n1] = lpB;
        }
        #pragma unroll
        for (int d = 0; d < 8; ++d) PACK2(zp[d], zA[d], zB[d]);
    }

    #pragma unroll 1
    for (int seg = 0; seg < NSEG; ++seg) {
        const float dt    = (ts[seg + 1] - ts[seg]) * 0.25f;
        const float hdt   = 0.5f * dt;
        const float sixth = dt * (1.0f / 6.0f);
        const float two   = 2.0f;
        u64p hdt2, dt2, sixth2, two2;
        PACK2(hdt2, hdt, hdt);
        PACK2(dt2, dt, dt);
        PACK2(sixth2, sixth, sixth);
        PACK2(two2, two, two);

        #pragma unroll 1
        for (int sub = 0; sub < 4; ++sub) {
            const int j = seg * 4 + sub;

            __syncthreads();   // previous substep done before slots overwritten
            if (j == 0) {      // load times 0,1,2 into slots 0,1,2 (contiguous)
                const float4* src = (const float4*)g_params;
                float4* dst = (float4*)sp;
                for (int q = tid; q < 3 * (PSTRIDE / 4); q += 64) dst[q] = src[q];
            } else {           // time 2j already resident; load 2j+1 and 2j+2
                const int tm = 2 * j + 1, te = 2 * j + 2;
                const float4* s1 = (const float4*)(g_params + (size_t)tm * PSTRIDE);
                const float4* s2 = (const float4*)(g_params + (size_t)te * PSTRIDE);
                float4* d1 = (float4*)(sp + (size_t)(tm % 3) * PSTRIDE);
                float4* d2 = (float4*)(sp + (size_t)(te % 3) * PSTRIDE);
                for (int q = tid; q < PSTRIDE / 4; q += 64) { d1[q] = s1[q]; d2[q] = s2[q]; }
            }
            __syncthreads();

            const float S0 = g_stot[2 * j];
            const float S1 = g_stot[2 * j + 1];
            const float S2 = g_stot[2 * j + 2];
            const float* pA = sp + (size_t)((2 * j)     % 3) * PSTRIDE;
            const float* pM = sp + (size_t)((2 * j + 1) % 3) * PSTRIDE;
            const float* pE = sp + (size_t)((2 * j + 2) % 3) * PSTRIDE;

            u64p kp[8], az[8], zs[8];
            float klA, klB, alA, alB;

            // k1
            rhs_eval2(pA, S0, zp, kp, klA, klB);
            #pragma unroll
            for (int d = 0; d < 8; ++d) {
                az[d] = kp[d];
                FMA2(zs[d], hdt2, kp[d], zp[d]);
            }
            alA = klA; alB = klB;
            // k2
            rhs_eval2(pM, S1, zs, kp, klA, klB);
            #pragma unroll
            for (int d = 0; d < 8; ++d) {
                FMA2(az[d], two2, kp[d], az[d]);
                FMA2(zs[d], hdt2, kp[d], zp[d]);
            }
            alA = fmaf(two, klA, alA); alB = fmaf(two, klB, alB);
            // k3
            rhs_eval2(pM, S1, zs, kp, klA, klB);
            #pragma unroll
            for (int d = 0; d < 8; ++d) {
                FMA2(az[d], two2, kp[d], az[d]);
                FMA2(zs[d], dt2, kp[d], zp[d]);
            }
            alA = fmaf(two, klA, alA); alB = fmaf(two, klB, alB);
            // k4
            rhs_eval2(pE, S2, zs, kp, klA, klB);
            #pragma unroll
            for (int d = 0; d < 8; ++d) {
                u64p tsum;
                ADD2(tsum, az[d], kp[d]);
                FMA2(zp[d], sixth2, tsum, zp[d]);
            }
            lpA = fmaf(sixth, alA + klA, lpA);
            lpB = fmaf(sixth, alB + klB, lpB);
        }

        // unpack and write this segment's state
        {
            float zA[8], zB[8];
            #pragma unroll
            for (int d = 0; d < 8; ++d) UNPACK2(zA[d], zB[d], zp[d]);
            if (act0) {
                const size_t zo = ((size_t)(seg + 1) * N + n0) * DD;
                *(float4*)(out + zo)     = make_float4(zA[0], zA[1], zA[2], zA[3]);
                *(float4*)(out + zo + 4) = make_float4(zA[4], zA[5], zA[6], zA[7]);
                out[LOFF + (size_t)(seg + 1) * N + n0] = lpA;
            }
            if (act1) {
                const size_t zo = ((size_t)(seg + 1) * N + n1) * DD;
                *(float4*)(out + zo)     = make_float4(zB[0], zB[1], zB[2], zB[3]);
                *(float4*)(out + zo + 4) = make_float4(zB[4], zB[5], zB[6], zB[7]);
                out[LOFF + (size_t)(seg + 1) * N + n1] = lpB;
            }
        }
    }
}

// ---------------------------------------------------------------------------
// Launch. Inputs (metadata order): ts, z0, logp_diff_t0, w1, b1, w2, b2, w3, b3.
// Output: concat(zt[T,N,D], logp_t[T,N,1]) as float32.
// ---------------------------------------------------------------------------
extern "C" void kernel_launch(void* const* d_in, const int* in_sizes, int n_in,
                              void* d_out, int out_size)
{
    const float* ts  = (const float*)d_in[0];
    const float* z0  = (const float*)d_in[1];
    const float* lp0 = (const float*)d_in[2];
    const float* w1  = (const float*)d_in[3];
    const float* b1  = (const float*)d_in[4];
    const float* w2  = (const float*)d_in[5];
    const float* b2  = (const float*)d_in[6];
    const float* w3  = (const float*)d_in[7];
    const float* b3  = (const float*)d_in[8];

    const int N = in_sizes[1] / DD;

    hyper_kernel<<<NTIMES, 256>>>(ts, w1, b1, w2, b2, w3, b3);

    const int blocks = (N + 127) / 128;   // 2 samples per thread, 64 threads/block
    cnf_kernel<<<blocks, 64>>>(ts, z0, lp0, (float*)d_out, N);

    (void)n_in; (void)out_size;
}